// round 7
// baseline (speedup 1.0000x reference)
#include <cuda_runtime.h>
#include <math.h>

#define NN 30000
#define EE 480000
#define HID 256
#define HEADS 8
#define LAYERS 6
#define BN_EPS 1e-5f

// ---------------- scratch ----------------
__device__ float g_h[NN * HID];
__device__ float g_xl[NN * HID];
__device__ float g_xr[NN * HID];
__device__ float g_agg[NN * HID];
__device__ float g_t1[NN * 128];
__device__ float g_den[NN * HEADS];
// edge-chain precompute: ep_i = edge_attr @ R_i + r_i
__device__ float g_R[LAYERS * 10 * HID];
__device__ float g_r[LAYERS * HID];
__device__ float g_Ach[LAYERS * 10 * HID];
__device__ float g_bch[LAYERS * HID];
// CSR by destination
__device__ int g_cnt[NN];
__device__ int g_rowptr[NN + 1];
__device__ int g_pos[NN];
__device__ int g_eidx[EE];

// ---------------- generic SGEMM (encoder K=13, final N=128) ----------------
__global__ __launch_bounds__(256) void sgemm(
    const float* __restrict__ A, const float* __restrict__ B,
    const float* __restrict__ bias, float* __restrict__ C,
    int M, int N, int K, float slope)
{
    const int BM = 128, BNt = 128, BK = 8;
    __shared__ float As[BK][BM];
    __shared__ float Bs[BK][BNt];
    int tid = threadIdx.x;
    int tx = tid & 15, ty = tid >> 4;
    int rowBase = blockIdx.y * BM, colBase = blockIdx.x * BNt;
    float acc[8][8];
#pragma unroll
    for (int i = 0; i < 8; i++)
#pragma unroll
        for (int j = 0; j < 8; j++) acc[i][j] = 0.f;
    for (int k0 = 0; k0 < K; k0 += BK) {
#pragma unroll
        for (int it = 0; it < 4; it++) {
            int idx = tid + it * 256;
            int m = idx >> 3, kk = idx & 7;
            int gr = rowBase + m, gc = k0 + kk;
            As[kk][m] = (gr < M && gc < K) ? A[(size_t)gr * K + gc] : 0.f;
        }
#pragma unroll
        for (int it = 0; it < 4; it++) {
            int idx = tid + it * 256;
            int kk = idx >> 7, n = idx & 127;
            int gr = k0 + kk, gc = colBase + n;
            Bs[kk][n] = (gr < K && gc < N) ? B[(size_t)gr * N + gc] : 0.f;
        }
        __syncthreads();
#pragma unroll
        for (int kk = 0; kk < BK; kk++) {
            float a[8], b[8];
#pragma unroll
            for (int i = 0; i < 8; i++) a[i] = As[kk][ty * 8 + i];
#pragma unroll
            for (int j = 0; j < 8; j++) b[j] = Bs[kk][tx * 8 + j];
#pragma unroll
            for (int i = 0; i < 8; i++)
#pragma unroll
                for (int j = 0; j < 8; j++) acc[i][j] += a[i] * b[j];
        }
        __syncthreads();
    }
#pragma unroll
    for (int i = 0; i < 8; i++) {
        int gr = rowBase + ty * 8 + i;
        if (gr >= M) continue;
#pragma unroll
        for (int j = 0; j < 8; j++) {
            int gc = colBase + tx * 8 + j;
            if (gc >= N) continue;
            float v = acc[i][j];
            if (bias) v += bias[gc];
            v = (v >= 0.f) ? v : slope * v;
            C[(size_t)gr * N + gc] = v;
        }
    }
}

// ---------------- TF32 tensor-core GEMM (dual output: Wl->xl, Wr->xr) ----------------
__device__ __forceinline__ float to_tf32(float x) {
    unsigned int u;
    asm("cvt.rna.tf32.f32 %0, %1;" : "=r"(u) : "f"(x));
    return __uint_as_float(u);
}

__global__ __launch_bounds__(256, 2) void gemm_tf32_dual(
    const float* __restrict__ A,
    const float* __restrict__ B0, const float* __restrict__ bias0, float* __restrict__ C0,
    const float* __restrict__ B1, const float* __restrict__ bias1, float* __restrict__ C1,
    int M)
{
    __shared__ float As[128][20];
    __shared__ float Bs[16][136];

    int which = blockIdx.x >> 1;
    const float* B    = which ? B1 : B0;
    const float* bias = which ? bias1 : bias0;
    float*       C    = which ? C1 : C0;

    int tid = threadIdx.x;
    int warp = tid >> 5, lane = tid & 31;
    int wm = (warp & 1) * 64;
    int wn = (warp >> 1) * 32;
    int rowBase = blockIdx.y * 128;
    int colBase = (blockIdx.x & 1) * 128;
    int lr = lane >> 2;
    int lc = lane & 3;

    float acc[4][4][4];
#pragma unroll
    for (int a = 0; a < 4; a++)
#pragma unroll
        for (int b = 0; b < 4; b++)
#pragma unroll
            for (int cc = 0; cc < 4; cc++) acc[a][b][cc] = 0.f;

    for (int k0 = 0; k0 < 256; k0 += 16) {
        float4 va[2], vb[2];
#pragma unroll
        for (int it = 0; it < 2; it++) {
            int idx = tid + it * 256;
            int r = idx >> 2;
            int kq = (idx & 3) << 2;
            int gr = rowBase + r;
            va[it] = make_float4(0.f, 0.f, 0.f, 0.f);
            if (gr < M) va[it] = *(const float4*)(A + (size_t)gr * 256 + k0 + kq);
        }
#pragma unroll
        for (int it = 0; it < 2; it++) {
            int idx = tid + it * 256;
            int kk = idx >> 5;
            int nq = (idx & 31) << 2;
            vb[it] = *(const float4*)(B + (size_t)(k0 + kk) * 256 + colBase + nq);
        }
#pragma unroll
        for (int it = 0; it < 2; it++) {
            int idx = tid + it * 256;
            int r = idx >> 2;
            int kq = (idx & 3) << 2;
            float4 v = va[it];
            v.x = to_tf32(v.x); v.y = to_tf32(v.y);
            v.z = to_tf32(v.z); v.w = to_tf32(v.w);
            *(float4*)&As[r][kq] = v;
        }
#pragma unroll
        for (int it = 0; it < 2; it++) {
            int idx = tid + it * 256;
            int kk = idx >> 5;
            int nq = (idx & 31) << 2;
            float4 v = vb[it];
            v.x = to_tf32(v.x); v.y = to_tf32(v.y);
            v.z = to_tf32(v.z); v.w = to_tf32(v.w);
            *(float4*)&Bs[kk][nq] = v;
        }
        __syncthreads();
#pragma unroll
        for (int kk = 0; kk < 16; kk += 8) {
            unsigned int af[4][4], bf[4][2];
#pragma unroll
            for (int mt = 0; mt < 4; mt++) {
                int m0 = wm + mt * 16;
                af[mt][0] = __float_as_uint(As[m0 + lr][kk + lc]);
                af[mt][1] = __float_as_uint(As[m0 + 8 + lr][kk + lc]);
                af[mt][2] = __float_as_uint(As[m0 + lr][kk + 4 + lc]);
                af[mt][3] = __float_as_uint(As[m0 + 8 + lr][kk + 4 + lc]);
            }
#pragma unroll
            for (int nt = 0; nt < 4; nt++) {
                int n0 = wn + nt * 8;
                bf[nt][0] = __float_as_uint(Bs[kk + lc][n0 + lr]);
                bf[nt][1] = __float_as_uint(Bs[kk + 4 + lc][n0 + lr]);
            }
#pragma unroll
            for (int mt = 0; mt < 4; mt++)
#pragma unroll
                for (int nt = 0; nt < 4; nt++) {
                    asm volatile(
                        "mma.sync.aligned.m16n8k8.row.col.f32.tf32.tf32.f32 "
                        "{%0,%1,%2,%3}, {%4,%5,%6,%7}, {%8,%9}, {%0,%1,%2,%3};"
                        : "+f"(acc[mt][nt][0]), "+f"(acc[mt][nt][1]),
                          "+f"(acc[mt][nt][2]), "+f"(acc[mt][nt][3])
                        : "r"(af[mt][0]), "r"(af[mt][1]), "r"(af[mt][2]), "r"(af[mt][3]),
                          "r"(bf[nt][0]), "r"(bf[nt][1]));
                }
        }
        __syncthreads();
    }

#pragma unroll
    for (int mt = 0; mt < 4; mt++)
#pragma unroll
        for (int nt = 0; nt < 4; nt++) {
            int r0 = rowBase + wm + mt * 16 + lr;
            int c0 = colBase + wn + nt * 8 + lc * 2;
            float b0 = bias[c0], b1 = bias[c0 + 1];
            if (r0 < M) {
                C[(size_t)r0 * 256 + c0]     = acc[mt][nt][0] + b0;
                C[(size_t)r0 * 256 + c0 + 1] = acc[mt][nt][1] + b1;
            }
            if (r0 + 8 < M) {
                C[(size_t)(r0 + 8) * 256 + c0]     = acc[mt][nt][2] + b0;
                C[(size_t)(r0 + 8) * 256 + c0 + 1] = acc[mt][nt][3] + b1;
            }
        }
}

// ---------------- precompute: sequential A/b chain (one block) ----------------
__global__ __launch_bounds__(256) void chain_kernel(
    const float* __restrict__ edge_W, const float* __restrict__ edge_b,
    const float* __restrict__ Weu, const float* __restrict__ beu,
    float* __restrict__ Ach, float* __restrict__ bch)
{
    __shared__ float Aw[10][HID];
    __shared__ float bw[HID];
    int c = threadIdx.x;
#pragma unroll
    for (int r = 0; r < 10; r++) Aw[r][c] = edge_W[r * HID + c];
    bw[c] = edge_b[c];
    __syncthreads();
#pragma unroll
    for (int r = 0; r < 10; r++) Ach[r * HID + c] = Aw[r][c];
    bch[c] = bw[c];
    for (int i = 0; i < LAYERS - 1; i++) {
        const float* W = Weu + (size_t)i * HID * HID;
        float acc[10];
#pragma unroll
        for (int r = 0; r < 10; r++) acc[r] = 0.f;
        float accB = beu[i * HID + c];
        for (int k = 0; k < HID; k++) {
            float w = W[(size_t)k * HID + c];
#pragma unroll
            for (int r = 0; r < 10; r++) acc[r] += Aw[r][k] * w;
            accB += bw[k] * w;
        }
        __syncthreads();
#pragma unroll
        for (int r = 0; r < 10; r++) Aw[r][c] = acc[r];
        bw[c] = accB;
        __syncthreads();
        float* Ao = Ach + (size_t)(i + 1) * 10 * HID;
#pragma unroll
        for (int r = 0; r < 10; r++) Ao[r * HID + c] = acc[r];
        bch[(i + 1) * HID + c] = accB;
    }
}

// ---------------- precompute: R_i = A_i @ We_i, r_i = b_i @ We_i ----------------
__global__ __launch_bounds__(256) void proj_kernel(
    const float* __restrict__ Ach, const float* __restrict__ bch,
    const float* __restrict__ We, float* __restrict__ R, float* __restrict__ rr)
{
    int i = blockIdx.x;
    int c = threadIdx.x;
    __shared__ float Aw[10][HID];
    __shared__ float bw[HID];
#pragma unroll
    for (int r = 0; r < 10; r++) Aw[r][c] = Ach[(size_t)i * 10 * HID + r * HID + c];
    bw[c] = bch[i * HID + c];
    __syncthreads();
    const float* W = We + (size_t)i * HID * HID;
    float acc[10];
#pragma unroll
    for (int r = 0; r < 10; r++) acc[r] = 0.f;
    float accB = 0.f;
    for (int k = 0; k < HID; k++) {
        float w = W[(size_t)k * HID + c];
#pragma unroll
        for (int r = 0; r < 10; r++) acc[r] += Aw[r][k] * w;
        accB += bw[k] * w;
    }
#pragma unroll
    for (int r = 0; r < 10; r++) R[(size_t)i * 10 * HID + r * HID + c] = acc[r];
    rr[i * HID + c] = accB;
}

// ---------------- CSR build ----------------
__global__ void hist_kernel(const int* __restrict__ dst, int* __restrict__ cnt)
{
    int e = blockIdx.x * blockDim.x + threadIdx.x;
    if (e < EE) atomicAdd(&cnt[dst[e]], 1);
}

__global__ __launch_bounds__(1024) void scan_kernel(
    const int* __restrict__ cnt, int* __restrict__ rowptr, int* __restrict__ pos)
{
    __shared__ int ssum[1024];
    int t = threadIdx.x;
    const int chunk = (NN + 1023) / 1024;   // 30
    int beg = t * chunk;
    int end = beg + chunk; if (end > NN) end = NN;
    int s = 0;
    for (int i = beg; i < end; i++) s += cnt[i];
    ssum[t] = s;
    __syncthreads();
    for (int off = 1; off < 1024; off <<= 1) {
        int v = (t >= off) ? ssum[t - off] : 0;
        __syncthreads();
        ssum[t] += v;
        __syncthreads();
    }
    int run = (t == 0) ? 0 : ssum[t - 1];
    for (int i = beg; i < end; i++) {
        rowptr[i] = run;
        pos[i] = run;
        run += cnt[i];
    }
    if (t == 1023) rowptr[NN] = run;
}

__global__ void scatter_kernel(const int* __restrict__ dst,
                               int* __restrict__ pos, int* __restrict__ eidx)
{
    int e = blockIdx.x * blockDim.x + threadIdx.x;
    if (e < EE) {
        int slot = atomicAdd(&pos[dst[e]], 1);
        eidx[slot] = e;
    }
}

__device__ __forceinline__ float leaky02(float v) { return v >= 0.f ? v : 0.2f * v; }

// ---------------- CSR edge pass: one node per block, atomic-free ----------------
// warp = head (32 channels), lane = channel-in-head. Registers hold xr[d], R col,
// agg and den accumulators. xl gathers hit L2 (xl is 30MB, L2-resident).
__global__ __launch_bounds__(256) void edge_csr_kernel(
    const float* __restrict__ xl, const float* __restrict__ xr,
    const float* __restrict__ eattr, const float* __restrict__ R,
    const float* __restrict__ rv, const float* __restrict__ att,
    const int* __restrict__ rowptr, const int* __restrict__ eidx,
    const int* __restrict__ src,
    float* __restrict__ den, float* __restrict__ agg)
{
    int n = blockIdx.x;
    int t = threadIdx.x;             // channel 0..255
    int w = t >> 5, lane = t & 31;

    float xr_c = xr[(size_t)n * HID + t];
    float rvc  = rv[t];
    float attc = att[t];
    float Rk[10];
#pragma unroll
    for (int k = 0; k < 10; k++) Rk[k] = R[k * HID + t];

    int beg = rowptr[n], end = rowptr[n + 1];
    float accv = 0.f, denv = 0.f;

    for (int i = beg; i < end; i++) {
        int e = eidx[i];
        int s = src[e];
        float eav = (lane < 10) ? eattr[(size_t)e * 10 + lane] : 0.f;
        float ep = rvc;
#pragma unroll
        for (int k = 0; k < 10; k++)
            ep += __shfl_sync(0xffffffffu, eav, k) * Rk[k];
        float xlv = xl[(size_t)s * HID + t];
        float m = leaky02(xlv + xr_c + ep);
        float p = m * attc;
#pragma unroll
        for (int off = 16; off; off >>= 1) p += __shfl_xor_sync(0xffffffffu, p, off);
        float v = 0.f;
        if (lane == 0) v = expf(p);          // one MUFU per warp, not 32
        v = __shfl_sync(0xffffffffu, v, 0);
        accv += xlv * v;
        denv += v;
    }

    agg[(size_t)n * HID + t] = accv;
    if (lane == 0) den[n * HEADS + w] = denv;
}

// ---------------- node update: normalize, conv bias, BN(eval), leaky, residual ----------------
__global__ void node_update_kernel(
    const float* __restrict__ agg, const float* __restrict__ den,
    const float* __restrict__ conv_b,
    const float* __restrict__ bn_g, const float* __restrict__ bn_b,
    const float* __restrict__ bn_rm, const float* __restrict__ bn_rv,
    float* __restrict__ h, int layer)
{
    int i = blockIdx.x * blockDim.x + threadIdx.x;
    if (i >= NN * HID) return;
    int c = i & (HID - 1);
    int node = i >> 8;
    int hd = c >> 5;
    float v = agg[i] / (den[node * HEADS + hd] + 1e-16f) + conv_b[c];
    v = (v - bn_rm[c]) * rsqrtf(bn_rv[c] + BN_EPS) * bn_g[c] + bn_b[c];
    v = (v >= 0.f) ? v : 0.01f * v;
    if (layer >= 1) v += h[i];
    h[i] = v;
}

// ---------------- final projection ----------------
__global__ void final_out_kernel(
    const float* __restrict__ t1, const float* __restrict__ W2,
    const float* __restrict__ b2, float* __restrict__ out)
{
    int gw = (blockIdx.x * blockDim.x + threadIdx.x) >> 5;
    int lane = threadIdx.x & 31;
    if (gw >= NN) return;
    const float* row = t1 + (size_t)gw * 128;
    float acc = 0.f;
#pragma unroll
    for (int k = lane; k < 128; k += 32) acc += row[k] * W2[k];
#pragma unroll
    for (int off = 16; off; off >>= 1) acc += __shfl_xor_sync(0xffffffffu, acc, off);
    if (lane == 0) out[gw] = acc + b2[0];
}

// ---------------- launch ----------------
extern "C" void kernel_launch(void* const* d_in, const int* in_sizes, int n_in,
                              void* d_out, int out_size)
{
    const float* x         = (const float*)d_in[0];
    const int*   ei        = (const int*)  d_in[1];
    const float* edge_attr = (const float*)d_in[2];
    const float* node_W    = (const float*)d_in[3];
    const float* node_b    = (const float*)d_in[4];
    const float* edge_W    = (const float*)d_in[5];
    const float* edge_b    = (const float*)d_in[6];
    const float* Wl        = (const float*)d_in[7];
    const float* bl        = (const float*)d_in[8];
    const float* Wr        = (const float*)d_in[9];
    const float* br        = (const float*)d_in[10];
    const float* We        = (const float*)d_in[11];
    const float* att       = (const float*)d_in[12];
    const float* conv_b    = (const float*)d_in[13];
    const float* Weu       = (const float*)d_in[14];
    const float* beu       = (const float*)d_in[15];
    const float* bn_g      = (const float*)d_in[16];
    const float* bn_b      = (const float*)d_in[17];
    const float* bn_rm     = (const float*)d_in[18];
    const float* bn_rv     = (const float*)d_in[19];
    const float* out_W1    = (const float*)d_in[20];
    const float* out_b1    = (const float*)d_in[21];
    const float* out_W2    = (const float*)d_in[22];
    const float* out_b2    = (const float*)d_in[23];

    const int* src = ei;
    const int* dst = ei + EE;

    float *h, *xl, *xr, *agg, *t1, *den, *R, *r, *Ach, *bch;
    int *cnt, *rowptr, *pos, *eidx;
    cudaGetSymbolAddress((void**)&h,      g_h);
    cudaGetSymbolAddress((void**)&xl,     g_xl);
    cudaGetSymbolAddress((void**)&xr,     g_xr);
    cudaGetSymbolAddress((void**)&agg,    g_agg);
    cudaGetSymbolAddress((void**)&t1,     g_t1);
    cudaGetSymbolAddress((void**)&den,    g_den);
    cudaGetSymbolAddress((void**)&R,      g_R);
    cudaGetSymbolAddress((void**)&r,      g_r);
    cudaGetSymbolAddress((void**)&Ach,    g_Ach);
    cudaGetSymbolAddress((void**)&bch,    g_bch);
    cudaGetSymbolAddress((void**)&cnt,    g_cnt);
    cudaGetSymbolAddress((void**)&rowptr, g_rowptr);
    cudaGetSymbolAddress((void**)&pos,    g_pos);
    cudaGetSymbolAddress((void**)&eidx,   g_eidx);

    dim3 blk(256);
    dim3 gN((HID + 127) / 128, (NN + 127) / 128);
    dim3 gD(4, (NN + 127) / 128);
    dim3 gO(1, (NN + 127) / 128);

    // ---- CSR build (once per launch; reused by all 6 layers) ----
    cudaMemsetAsync(cnt, 0, NN * sizeof(int), 0);
    hist_kernel<<<EE / 256, 256>>>(dst, cnt);
    scan_kernel<<<1, 1024>>>(cnt, rowptr, pos);
    scatter_kernel<<<EE / 256, 256>>>(dst, pos, eidx);

    // ---- edge-chain precompute ----
    chain_kernel<<<1, 256>>>(edge_W, edge_b, Weu, beu, Ach, bch);
    proj_kernel<<<LAYERS, 256>>>(Ach, bch, We, R, r);

    // node encoder (K=13)
    sgemm<<<gN, blk>>>(x, node_W, node_b, h, NN, HID, 13, 1.f);

    for (int i = 0; i < LAYERS; i++) {
        const float* Wli = Wl + (size_t)i * HID * HID;
        const float* Wri = Wr + (size_t)i * HID * HID;

        gemm_tf32_dual<<<gD, blk>>>(h, Wli, bl + i * HID, xl,
                                       Wri, br + i * HID, xr, NN);

        edge_csr_kernel<<<NN, 256>>>(
            xl, xr, edge_attr,
            R + (size_t)i * 10 * HID, r + (size_t)i * HID,
            att + (size_t)i * HID,
            rowptr, eidx, src, den, agg);

        node_update_kernel<<<(NN * HID + 255) / 256, 256>>>(
            agg, den, conv_b + i * HID, bn_g + i * HID, bn_b + i * HID,
            bn_rm + i * HID, bn_rv + i * HID, h, i);
    }

    sgemm<<<gO, blk>>>(h, out_W1, out_b1, t1, NN, 128, HID, 0.01f);
    final_out_kernel<<<(NN * 32 + 255) / 256, 256>>>(t1, out_W2, out_b2, (float*)d_out);
}

// round 8
// speedup vs baseline: 1.3624x; 1.3624x over previous
#include <cuda_runtime.h>
#include <math.h>

#define NN 30000
#define EE 480000
#define HID 256
#define HEADS 8
#define LAYERS 6
#define BN_EPS 1e-5f

// ---------------- scratch ----------------
__device__ float g_h[NN * HID];
__device__ float g_xl[NN * HID];
__device__ float g_xr[NN * HID];
__device__ float g_agg[NN * HID];
__device__ float g_t1[NN * 128];
__device__ float g_den[NN * HEADS];
// edge-chain precompute: ep_i = edge_attr @ R_i + r_i
__device__ float g_R[LAYERS * 10 * HID];
__device__ float g_r[LAYERS * HID];
__device__ float g_Ach[LAYERS * 10 * HID];
__device__ float g_bch[LAYERS * HID];

// ---------------- generic SGEMM (encoder K=13) ----------------
__global__ __launch_bounds__(256) void sgemm(
    const float* __restrict__ A, const float* __restrict__ B,
    const float* __restrict__ bias, float* __restrict__ C,
    int M, int N, int K, float slope)
{
    const int BM = 128, BNt = 128, BK = 8;
    __shared__ float As[BK][BM];
    __shared__ float Bs[BK][BNt];
    int tid = threadIdx.x;
    int tx = tid & 15, ty = tid >> 4;
    int rowBase = blockIdx.y * BM, colBase = blockIdx.x * BNt;
    float acc[8][8];
#pragma unroll
    for (int i = 0; i < 8; i++)
#pragma unroll
        for (int j = 0; j < 8; j++) acc[i][j] = 0.f;
    for (int k0 = 0; k0 < K; k0 += BK) {
#pragma unroll
        for (int it = 0; it < 4; it++) {
            int idx = tid + it * 256;
            int m = idx >> 3, kk = idx & 7;
            int gr = rowBase + m, gc = k0 + kk;
            As[kk][m] = (gr < M && gc < K) ? A[(size_t)gr * K + gc] : 0.f;
        }
#pragma unroll
        for (int it = 0; it < 4; it++) {
            int idx = tid + it * 256;
            int kk = idx >> 7, n = idx & 127;
            int gr = k0 + kk, gc = colBase + n;
            Bs[kk][n] = (gr < K && gc < N) ? B[(size_t)gr * N + gc] : 0.f;
        }
        __syncthreads();
#pragma unroll
        for (int kk = 0; kk < BK; kk++) {
            float a[8], b[8];
#pragma unroll
            for (int i = 0; i < 8; i++) a[i] = As[kk][ty * 8 + i];
#pragma unroll
            for (int j = 0; j < 8; j++) b[j] = Bs[kk][tx * 8 + j];
#pragma unroll
            for (int i = 0; i < 8; i++)
#pragma unroll
                for (int j = 0; j < 8; j++) acc[i][j] += a[i] * b[j];
        }
        __syncthreads();
    }
#pragma unroll
    for (int i = 0; i < 8; i++) {
        int gr = rowBase + ty * 8 + i;
        if (gr >= M) continue;
#pragma unroll
        for (int j = 0; j < 8; j++) {
            int gc = colBase + tx * 8 + j;
            if (gc >= N) continue;
            float v = acc[i][j];
            if (bias) v += bias[gc];
            v = (v >= 0.f) ? v : slope * v;
            C[(size_t)gr * N + gc] = v;
        }
    }
}

// ---------------- TF32 helpers ----------------
__device__ __forceinline__ float to_tf32(float x) {
    unsigned int u;
    asm("cvt.rna.tf32.f32 %0, %1;" : "=r"(u) : "f"(x));
    return __uint_as_float(u);
}

// ---------------- TF32 dual GEMM: h@Wl->xl, h@Wr->xr (N=256) ----------------
__global__ __launch_bounds__(256, 2) void gemm_tf32_dual(
    const float* __restrict__ A,
    const float* __restrict__ B0, const float* __restrict__ bias0, float* __restrict__ C0,
    const float* __restrict__ B1, const float* __restrict__ bias1, float* __restrict__ C1,
    int M)
{
    __shared__ float As[128][20];
    __shared__ float Bs[16][136];

    int which = blockIdx.x >> 1;
    const float* B    = which ? B1 : B0;
    const float* bias = which ? bias1 : bias0;
    float*       C    = which ? C1 : C0;

    int tid = threadIdx.x;
    int warp = tid >> 5, lane = tid & 31;
    int wm = (warp & 1) * 64;
    int wn = (warp >> 1) * 32;
    int rowBase = blockIdx.y * 128;
    int colBase = (blockIdx.x & 1) * 128;
    int lr = lane >> 2;
    int lc = lane & 3;

    float acc[4][4][4];
#pragma unroll
    for (int a = 0; a < 4; a++)
#pragma unroll
        for (int b = 0; b < 4; b++)
#pragma unroll
            for (int cc = 0; cc < 4; cc++) acc[a][b][cc] = 0.f;

    for (int k0 = 0; k0 < 256; k0 += 16) {
        float4 va[2], vb[2];
#pragma unroll
        for (int it = 0; it < 2; it++) {
            int idx = tid + it * 256;
            int r = idx >> 2;
            int kq = (idx & 3) << 2;
            int gr = rowBase + r;
            va[it] = make_float4(0.f, 0.f, 0.f, 0.f);
            if (gr < M) va[it] = *(const float4*)(A + (size_t)gr * 256 + k0 + kq);
        }
#pragma unroll
        for (int it = 0; it < 2; it++) {
            int idx = tid + it * 256;
            int kk = idx >> 5;
            int nq = (idx & 31) << 2;
            vb[it] = *(const float4*)(B + (size_t)(k0 + kk) * 256 + colBase + nq);
        }
#pragma unroll
        for (int it = 0; it < 2; it++) {
            int idx = tid + it * 256;
            int r = idx >> 2;
            int kq = (idx & 3) << 2;
            float4 v = va[it];
            v.x = to_tf32(v.x); v.y = to_tf32(v.y);
            v.z = to_tf32(v.z); v.w = to_tf32(v.w);
            *(float4*)&As[r][kq] = v;
        }
#pragma unroll
        for (int it = 0; it < 2; it++) {
            int idx = tid + it * 256;
            int kk = idx >> 5;
            int nq = (idx & 31) << 2;
            float4 v = vb[it];
            v.x = to_tf32(v.x); v.y = to_tf32(v.y);
            v.z = to_tf32(v.z); v.w = to_tf32(v.w);
            *(float4*)&Bs[kk][nq] = v;
        }
        __syncthreads();
#pragma unroll
        for (int kk = 0; kk < 16; kk += 8) {
            unsigned int af[4][4], bf[4][2];
#pragma unroll
            for (int mt = 0; mt < 4; mt++) {
                int m0 = wm + mt * 16;
                af[mt][0] = __float_as_uint(As[m0 + lr][kk + lc]);
                af[mt][1] = __float_as_uint(As[m0 + 8 + lr][kk + lc]);
                af[mt][2] = __float_as_uint(As[m0 + lr][kk + 4 + lc]);
                af[mt][3] = __float_as_uint(As[m0 + 8 + lr][kk + 4 + lc]);
            }
#pragma unroll
            for (int nt = 0; nt < 4; nt++) {
                int n0 = wn + nt * 8;
                bf[nt][0] = __float_as_uint(Bs[kk + lc][n0 + lr]);
                bf[nt][1] = __float_as_uint(Bs[kk + 4 + lc][n0 + lr]);
            }
#pragma unroll
            for (int mt = 0; mt < 4; mt++)
#pragma unroll
                for (int nt = 0; nt < 4; nt++) {
                    asm volatile(
                        "mma.sync.aligned.m16n8k8.row.col.f32.tf32.tf32.f32 "
                        "{%0,%1,%2,%3}, {%4,%5,%6,%7}, {%8,%9}, {%0,%1,%2,%3};"
                        : "+f"(acc[mt][nt][0]), "+f"(acc[mt][nt][1]),
                          "+f"(acc[mt][nt][2]), "+f"(acc[mt][nt][3])
                        : "r"(af[mt][0]), "r"(af[mt][1]), "r"(af[mt][2]), "r"(af[mt][3]),
                          "r"(bf[nt][0]), "r"(bf[nt][1]));
                }
        }
        __syncthreads();
    }

#pragma unroll
    for (int mt = 0; mt < 4; mt++)
#pragma unroll
        for (int nt = 0; nt < 4; nt++) {
            int r0 = rowBase + wm + mt * 16 + lr;
            int c0 = colBase + wn + nt * 8 + lc * 2;
            float b0 = bias[c0], b1 = bias[c0 + 1];
            if (r0 < M) {
                C[(size_t)r0 * 256 + c0]     = acc[mt][nt][0] + b0;
                C[(size_t)r0 * 256 + c0 + 1] = acc[mt][nt][1] + b1;
            }
            if (r0 + 8 < M) {
                C[(size_t)(r0 + 8) * 256 + c0]     = acc[mt][nt][2] + b0;
                C[(size_t)(r0 + 8) * 256 + c0 + 1] = acc[mt][nt][3] + b1;
            }
        }
}

// ---------------- TF32 final GEMM: t1 = leaky01(h @ out_W1 + b1), N=128 ----------------
__global__ __launch_bounds__(256, 2) void gemm_tf32_final(
    const float* __restrict__ A, const float* __restrict__ B,
    const float* __restrict__ bias, float* __restrict__ C, int M)
{
    __shared__ float As[128][20];
    __shared__ float Bs[16][136];

    int tid = threadIdx.x;
    int warp = tid >> 5, lane = tid & 31;
    int wm = (warp & 1) * 64;
    int wn = (warp >> 1) * 32;
    int rowBase = blockIdx.y * 128;
    int lr = lane >> 2;
    int lc = lane & 3;

    float acc[4][4][4];
#pragma unroll
    for (int a = 0; a < 4; a++)
#pragma unroll
        for (int b = 0; b < 4; b++)
#pragma unroll
            for (int cc = 0; cc < 4; cc++) acc[a][b][cc] = 0.f;

    for (int k0 = 0; k0 < 256; k0 += 16) {
        float4 va[2], vb[2];
#pragma unroll
        for (int it = 0; it < 2; it++) {
            int idx = tid + it * 256;
            int r = idx >> 2;
            int kq = (idx & 3) << 2;
            int gr = rowBase + r;
            va[it] = make_float4(0.f, 0.f, 0.f, 0.f);
            if (gr < M) va[it] = *(const float4*)(A + (size_t)gr * 256 + k0 + kq);
        }
#pragma unroll
        for (int it = 0; it < 2; it++) {
            int idx = tid + it * 256;
            int kk = idx >> 5;
            int nq = (idx & 31) << 2;   // 0..124, covers N=128
            vb[it] = *(const float4*)(B + (size_t)(k0 + kk) * 128 + nq);
        }
#pragma unroll
        for (int it = 0; it < 2; it++) {
            int idx = tid + it * 256;
            int r = idx >> 2;
            int kq = (idx & 3) << 2;
            float4 v = va[it];
            v.x = to_tf32(v.x); v.y = to_tf32(v.y);
            v.z = to_tf32(v.z); v.w = to_tf32(v.w);
            *(float4*)&As[r][kq] = v;
        }
#pragma unroll
        for (int it = 0; it < 2; it++) {
            int idx = tid + it * 256;
            int kk = idx >> 5;
            int nq = (idx & 31) << 2;
            float4 v = vb[it];
            v.x = to_tf32(v.x); v.y = to_tf32(v.y);
            v.z = to_tf32(v.z); v.w = to_tf32(v.w);
            *(float4*)&Bs[kk][nq] = v;
        }
        __syncthreads();
#pragma unroll
        for (int kk = 0; kk < 16; kk += 8) {
            unsigned int af[4][4], bf[4][2];
#pragma unroll
            for (int mt = 0; mt < 4; mt++) {
                int m0 = wm + mt * 16;
                af[mt][0] = __float_as_uint(As[m0 + lr][kk + lc]);
                af[mt][1] = __float_as_uint(As[m0 + 8 + lr][kk + lc]);
                af[mt][2] = __float_as_uint(As[m0 + lr][kk + 4 + lc]);
                af[mt][3] = __float_as_uint(As[m0 + 8 + lr][kk + 4 + lc]);
            }
#pragma unroll
            for (int nt = 0; nt < 4; nt++) {
                int n0 = wn + nt * 8;
                bf[nt][0] = __float_as_uint(Bs[kk + lc][n0 + lr]);
                bf[nt][1] = __float_as_uint(Bs[kk + 4 + lc][n0 + lr]);
            }
#pragma unroll
            for (int mt = 0; mt < 4; mt++)
#pragma unroll
                for (int nt = 0; nt < 4; nt++) {
                    asm volatile(
                        "mma.sync.aligned.m16n8k8.row.col.f32.tf32.tf32.f32 "
                        "{%0,%1,%2,%3}, {%4,%5,%6,%7}, {%8,%9}, {%0,%1,%2,%3};"
                        : "+f"(acc[mt][nt][0]), "+f"(acc[mt][nt][1]),
                          "+f"(acc[mt][nt][2]), "+f"(acc[mt][nt][3])
                        : "r"(af[mt][0]), "r"(af[mt][1]), "r"(af[mt][2]), "r"(af[mt][3]),
                          "r"(bf[nt][0]), "r"(bf[nt][1]));
                }
        }
        __syncthreads();
    }

#pragma unroll
    for (int mt = 0; mt < 4; mt++)
#pragma unroll
        for (int nt = 0; nt < 4; nt++) {
            int r0 = rowBase + wm + mt * 16 + lr;
            int c0 = wn + nt * 8 + lc * 2;
            float b0 = bias[c0], b1 = bias[c0 + 1];
            float v0 = acc[mt][nt][0] + b0;
            float v1 = acc[mt][nt][1] + b1;
            float v2 = acc[mt][nt][2] + b0;
            float v3 = acc[mt][nt][3] + b1;
            v0 = (v0 >= 0.f) ? v0 : 0.01f * v0;
            v1 = (v1 >= 0.f) ? v1 : 0.01f * v1;
            v2 = (v2 >= 0.f) ? v2 : 0.01f * v2;
            v3 = (v3 >= 0.f) ? v3 : 0.01f * v3;
            if (r0 < M) {
                C[(size_t)r0 * 128 + c0]     = v0;
                C[(size_t)r0 * 128 + c0 + 1] = v1;
            }
            if (r0 + 8 < M) {
                C[(size_t)(r0 + 8) * 128 + c0]     = v2;
                C[(size_t)(r0 + 8) * 128 + c0 + 1] = v3;
            }
        }
}

// ---------------- precompute: one chain step [11,256]@[256,256] (rows 0-9=A, 10=bias) ----------------
__global__ __launch_bounds__(256) void chain_step(
    const float* __restrict__ Ain, const float* __restrict__ bin,
    const float* __restrict__ W, const float* __restrict__ bias_add,
    float* __restrict__ Aout, float* __restrict__ bout)
{
    int rrow = blockIdx.x;          // 0..10
    int c = threadIdx.x;
    __shared__ float av[HID];
    av[c] = (rrow < 10) ? Ain[rrow * HID + c] : bin[c];
    __syncthreads();
    float acc = 0.f;
#pragma unroll 8
    for (int k = 0; k < HID; k++) acc += av[k] * W[(size_t)k * HID + c];
    if (rrow < 10) Aout[rrow * HID + c] = acc;
    else           bout[c] = acc + bias_add[c];
}

// ---------------- precompute: R_i = A_i @ We_i, r_i = b_i @ We_i (grid 11 x 6) ----------------
__global__ __launch_bounds__(256) void proj_all(
    const float* __restrict__ Ach, const float* __restrict__ bch,
    const float* __restrict__ We, float* __restrict__ R, float* __restrict__ rr)
{
    int rrow = blockIdx.x;          // 0..10
    int layer = blockIdx.y;         // 0..5
    int c = threadIdx.x;
    __shared__ float av[HID];
    av[c] = (rrow < 10) ? Ach[(size_t)layer * 10 * HID + rrow * HID + c]
                        : bch[layer * HID + c];
    __syncthreads();
    const float* W = We + (size_t)layer * HID * HID;
    float acc = 0.f;
#pragma unroll 8
    for (int k = 0; k < HID; k++) acc += av[k] * W[(size_t)k * HID + c];
    if (rrow < 10) R[(size_t)layer * 10 * HID + rrow * HID + c] = acc;
    else           rr[layer * HID + c] = acc;
}

__device__ __forceinline__ float leaky02(float v) { return v >= 0.f ? v : 0.2f * v; }

// ---------------- fused edge pass (round-6 proven): ep + logits + exp + den + unnorm agg ----------------
__global__ __launch_bounds__(256) void edge_fused_kernel(
    const float4* __restrict__ xl4, const float4* __restrict__ xr4,
    const float* __restrict__ eattr, const float4* __restrict__ R4,
    const float4* __restrict__ rv4, const int* __restrict__ src,
    const int* __restrict__ dst, const float4* __restrict__ att4,
    float* __restrict__ den, float4* __restrict__ agg4)
{
    int e = blockIdx.x * 4 + threadIdx.y;
    int t = threadIdx.x;
    int s = src[e], d = dst[e];

    float4 acc = rv4[t];
    const float* ea = eattr + (size_t)e * 10;
#pragma unroll
    for (int k = 0; k < 10; k++) {
        float a = ea[k];
        float4 rrv = R4[k * 64 + t];
        acc.x += a * rrv.x; acc.y += a * rrv.y; acc.z += a * rrv.z; acc.w += a * rrv.w;
    }
    float4 l = xl4[(size_t)s * 64 + t];
    float4 rrv = xr4[(size_t)d * 64 + t];
    float4 m;
    m.x = leaky02(l.x + rrv.x + acc.x);
    m.y = leaky02(l.y + rrv.y + acc.y);
    m.z = leaky02(l.z + rrv.z + acc.z);
    m.w = leaky02(l.w + rrv.w + acc.w);
    float4 at = att4[t];
    float p = m.x * at.x + m.y * at.y + m.z * at.z + m.w * at.w;
#pragma unroll
    for (int off = 4; off; off >>= 1) p += __shfl_xor_sync(0xffffffffu, p, off);
    float v = expf(p);
    if ((t & 7) == 0) {
        int hh = t >> 3;
        atomicAdd(&den[d * HEADS + hh], v);
    }
    float4 w;
    w.x = l.x * v; w.y = l.y * v; w.z = l.z * v; w.w = l.w * v;
    float4* addr = agg4 + (size_t)d * 64 + t;
    asm volatile("red.global.add.v4.f32 [%0], {%1, %2, %3, %4};"
                 :: "l"(addr), "f"(w.x), "f"(w.y), "f"(w.z), "f"(w.w) : "memory");
}

// ---------------- node update: normalize, conv bias, BN(eval), leaky, residual ----------------
__global__ void node_update_kernel(
    const float* __restrict__ agg, const float* __restrict__ den,
    const float* __restrict__ conv_b,
    const float* __restrict__ bn_g, const float* __restrict__ bn_b,
    const float* __restrict__ bn_rm, const float* __restrict__ bn_rv,
    float* __restrict__ h, int layer)
{
    int i = blockIdx.x * blockDim.x + threadIdx.x;
    if (i >= NN * HID) return;
    int c = i & (HID - 1);
    int node = i >> 8;
    int hd = c >> 5;
    float v = agg[i] / (den[node * HEADS + hd] + 1e-16f) + conv_b[c];
    v = (v - bn_rm[c]) * rsqrtf(bn_rv[c] + BN_EPS) * bn_g[c] + bn_b[c];
    v = (v >= 0.f) ? v : 0.01f * v;
    if (layer >= 1) v += h[i];
    h[i] = v;
}

// ---------------- final projection to scalar ----------------
__global__ void final_out_kernel(
    const float* __restrict__ t1, const float* __restrict__ W2,
    const float* __restrict__ b2, float* __restrict__ out)
{
    int gw = (blockIdx.x * blockDim.x + threadIdx.x) >> 5;
    int lane = threadIdx.x & 31;
    if (gw >= NN) return;
    const float* row = t1 + (size_t)gw * 128;
    float acc = 0.f;
#pragma unroll
    for (int k = lane; k < 128; k += 32) acc += row[k] * W2[k];
#pragma unroll
    for (int off = 16; off; off >>= 1) acc += __shfl_xor_sync(0xffffffffu, acc, off);
    if (lane == 0) out[gw] = acc + b2[0];
}

// ---------------- launch ----------------
extern "C" void kernel_launch(void* const* d_in, const int* in_sizes, int n_in,
                              void* d_out, int out_size)
{
    const float* x         = (const float*)d_in[0];
    const int*   ei        = (const int*)  d_in[1];
    const float* edge_attr = (const float*)d_in[2];
    const float* node_W    = (const float*)d_in[3];
    const float* node_b    = (const float*)d_in[4];
    const float* edge_W    = (const float*)d_in[5];
    const float* edge_b    = (const float*)d_in[6];
    const float* Wl        = (const float*)d_in[7];
    const float* bl        = (const float*)d_in[8];
    const float* Wr        = (const float*)d_in[9];
    const float* br        = (const float*)d_in[10];
    const float* We        = (const float*)d_in[11];
    const float* att       = (const float*)d_in[12];
    const float* conv_b    = (const float*)d_in[13];
    const float* Weu       = (const float*)d_in[14];
    const float* beu       = (const float*)d_in[15];
    const float* bn_g      = (const float*)d_in[16];
    const float* bn_b      = (const float*)d_in[17];
    const float* bn_rm     = (const float*)d_in[18];
    const float* bn_rv     = (const float*)d_in[19];
    const float* out_W1    = (const float*)d_in[20];
    const float* out_b1    = (const float*)d_in[21];
    const float* out_W2    = (const float*)d_in[22];
    const float* out_b2    = (const float*)d_in[23];

    const int* src = ei;
    const int* dst = ei + EE;

    float *h, *xl, *xr, *agg, *t1, *den, *R, *r, *Ach, *bch;
    cudaGetSymbolAddress((void**)&h,   g_h);
    cudaGetSymbolAddress((void**)&xl,  g_xl);
    cudaGetSymbolAddress((void**)&xr,  g_xr);
    cudaGetSymbolAddress((void**)&agg, g_agg);
    cudaGetSymbolAddress((void**)&t1,  g_t1);
    cudaGetSymbolAddress((void**)&den, g_den);
    cudaGetSymbolAddress((void**)&R,   g_R);
    cudaGetSymbolAddress((void**)&r,   g_r);
    cudaGetSymbolAddress((void**)&Ach, g_Ach);
    cudaGetSymbolAddress((void**)&bch, g_bch);

    dim3 blk(256);
    dim3 gN((HID + 127) / 128, (NN + 127) / 128);
    dim3 gD(4, (NN + 127) / 128);
    dim3 gF(1, (NN + 127) / 128);

    // ---- edge-chain precompute: copy layer-0, 5 parallel-row chain steps, then all projections ----
    cudaMemcpyAsync(Ach, edge_W, 10 * HID * sizeof(float), cudaMemcpyDeviceToDevice, 0);
    cudaMemcpyAsync(bch, edge_b, HID * sizeof(float), cudaMemcpyDeviceToDevice, 0);
    for (int i = 0; i < LAYERS - 1; i++) {
        chain_step<<<11, 256>>>(
            Ach + (size_t)i * 10 * HID, bch + (size_t)i * HID,
            Weu + (size_t)i * HID * HID, beu + (size_t)i * HID,
            Ach + (size_t)(i + 1) * 10 * HID, bch + (size_t)(i + 1) * HID);
    }
    proj_all<<<dim3(11, LAYERS), 256>>>(Ach, bch, We, R, r);

    // node encoder (K=13)
    sgemm<<<gN, blk>>>(x, node_W, node_b, h, NN, HID, 13, 1.f);

    dim3 eblk(64, 4);
    int egrid = EE / 4;

    for (int i = 0; i < LAYERS; i++) {
        const float* Wli = Wl + (size_t)i * HID * HID;
        const float* Wri = Wr + (size_t)i * HID * HID;

        gemm_tf32_dual<<<gD, blk>>>(h, Wli, bl + i * HID, xl,
                                       Wri, br + i * HID, xr, NN);

        cudaMemsetAsync(den, 0, (size_t)NN * HEADS * sizeof(float), 0);
        cudaMemsetAsync(agg, 0, (size_t)NN * HID * sizeof(float), 0);

        edge_fused_kernel<<<egrid, eblk>>>(
            (const float4*)xl, (const float4*)xr, edge_attr,
            (const float4*)(R + (size_t)i * 10 * HID),
            (const float4*)(r + (size_t)i * HID),
            src, dst, (const float4*)(att + (size_t)i * HID), den, (float4*)agg);

        node_update_kernel<<<(NN * HID + 255) / 256, 256>>>(
            agg, den, conv_b + i * HID, bn_g + i * HID, bn_b + i * HID,
            bn_rm + i * HID, bn_rv + i * HID, h, i);
    }

    gemm_tf32_final<<<gF, blk>>>(h, out_W1, out_b1, t1, NN);
    final_out_kernel<<<(NN * 32 + 255) / 256, 256>>>(t1, out_W2, out_b2, (float*)d_out);
}